// round 1
// baseline (speedup 1.0000x reference)
#include <cuda_runtime.h>
#include <math.h>

#define BATCH 8
#define DD 24
#define HH 64
#define WW 128
#define HW (HH*WW)

// ---------------- scratch (device globals; no allocations allowed) ----------------
__device__ float g_cv[BATCH*8*DD*HH*WW];        // cost volume (B,8,24,64,128)
__device__ float g_x1[BATCH*16*DD*HH*WW];       // conv1 raw
__device__ float g_x1n[BATCH*16*DD*HH*WW];      // conv1 GN+silu
__device__ float g_x2[BATCH*16*DD*HH*WW];       // conv2 raw
__device__ float g_x2n[BATCH*16*DD*HH*WW];      // conv2 GN+silu
__device__ float g_logits[BATCH*DD*HH*WW];      // conv3 output
__device__ float g_feat[BATCH*16*HH*WW];        // feat conv raw
__device__ double g_stats[3*BATCH*8*2];         // [layer][b][group][{sum,sumsq}]

// ---------------- zero stats ----------------
__global__ void k_zero_stats() {
    int i = threadIdx.x;
    if (i < 3*BATCH*8*2) g_stats[i] = 0.0;
}

// ---------------- cost volume ----------------
// grid = B*8*H, block = 128 (one thread per w)
__global__ void __launch_bounds__(128) k_costvol(const float* __restrict__ fL,
                                                 const float* __restrict__ fR) {
    __shared__ float sR[16*128];
    int x = blockIdx.x;
    int h = x & 63;
    int g = (x >> 6) & 7;
    int b = x >> 9;
    int tid = threadIdx.x;

    const float* baseL = fL + (((size_t)(b*128 + g*16))*HH + h)*WW;
    const float* baseR = fR + (((size_t)(b*128 + g*16))*HH + h)*WW;
    float l[16];
#pragma unroll
    for (int c = 0; c < 16; c++) {
        l[c] = baseL[(size_t)c*HW + tid];
        sR[c*128 + tid] = baseR[(size_t)c*HW + tid];
    }
    __syncthreads();

    float* ov = g_cv + (((size_t)(b*8 + g)*DD)*HH + h)*WW + tid;
    for (int d = 0; d < DD; d++) {
        float s = 0.f;
        if (tid >= d) {
#pragma unroll
            for (int c = 0; c < 16; c++) s += l[c] * sR[c*128 + tid - d];
            s *= 0.0625f;
        }
        ov[(size_t)d*HW] = s;
    }
}

// ---------------- conv3d, 16 output channels, fused GN stats ----------------
// LAYER 0: g_cv(CIN=8) -> g_x1 ; LAYER 1: g_x1n(CIN=16) -> g_x2
// grid = B*24*16, block = 128; thread: 8 oc x 8 w outputs
template<int LAYER>
__global__ void __launch_bounds__(128, 4) k_conv3d16(const float* __restrict__ wts) {
    constexpr int CIN = (LAYER == 0) ? 8 : 16;
    const float* in = (LAYER == 0) ? g_cv : g_x1n;
    float* out = (LAYER == 0) ? g_x1 : g_x2;
    double* stats = g_stats + LAYER*128;

    __shared__ __align__(16) float swt[CIN*432];   // [ic][tap][oc]
    __shared__ float sred[16];
    int tid = threadIdx.x;
    for (int i = tid; i < CIN*432; i += 128) {
        int ic = i / 432; int r = i - ic*432; int tap = r >> 4; int oc = r & 15;
        swt[i] = wts[(oc*CIN + ic)*27 + tap];
    }
    if (tid < 16) sred[tid] = 0.f;
    __syncthreads();

    int x = blockIdx.x;
    int ht = x & 15;
    int d = (x >> 4) % 24;
    int b = x / 384;

    int wt = tid & 15, hr = (tid >> 4) & 3, os = tid >> 6;
    int w0 = wt << 3, h = (ht << 2) + hr, oc0 = os << 3;

    float acc[8][8];
#pragma unroll
    for (int o = 0; o < 8; o++)
#pragma unroll
        for (int j = 0; j < 8; j++) acc[o][j] = 0.f;

    const float* inb = in + (size_t)b*CIN*DD*HW;
    for (int ic = 0; ic < CIN; ic++) {
        const float* inc = inb + (size_t)ic*DD*HW;
#pragma unroll
        for (int kd = 0; kd < 3; kd++) {
            int zd = d + kd - 1;
            if ((unsigned)zd >= (unsigned)DD) continue;
#pragma unroll
            for (int kh = 0; kh < 3; kh++) {
                int zh = h + kh - 1;
                if ((unsigned)zh >= (unsigned)HH) continue;
                const float* row = inc + ((size_t)zd*HH + zh)*WW + w0;
                float r[10];
                r[0] = (w0 == 0) ? 0.f : __ldg(row - 1);
                float4 va = *(const float4*)row;
                float4 vb = *(const float4*)(row + 4);
                r[1] = va.x; r[2] = va.y; r[3] = va.z; r[4] = va.w;
                r[5] = vb.x; r[6] = vb.y; r[7] = vb.z; r[8] = vb.w;
                r[9] = (w0 == 120) ? 0.f : __ldg(row + 8);
                int tb = (kd*3 + kh)*3;
#pragma unroll
                for (int kw = 0; kw < 3; kw++) {
                    const float4* wp = (const float4*)(swt + ((ic*27 + tb + kw) << 4) + oc0);
                    float4 wA = wp[0], wB = wp[1];
                    float wv[8] = {wA.x, wA.y, wA.z, wA.w, wB.x, wB.y, wB.z, wB.w};
#pragma unroll
                    for (int o = 0; o < 8; o++)
#pragma unroll
                        for (int j = 0; j < 8; j++)
                            acc[o][j] = fmaf(wv[o], r[j + kw], acc[o][j]);
                }
            }
        }
    }

    // store + per-group partial stats
    float gs[4], gs2[4];
#pragma unroll
    for (int i = 0; i < 4; i++) { gs[i] = 0.f; gs2[i] = 0.f; }
#pragma unroll
    for (int o = 0; o < 8; o++) {
        int oc = oc0 + o;
        float* orow = out + ((((size_t)b*16 + oc)*DD + d)*HH + h)*WW + w0;
        *(float4*)orow       = make_float4(acc[o][0], acc[o][1], acc[o][2], acc[o][3]);
        *(float4*)(orow + 4) = make_float4(acc[o][4], acc[o][5], acc[o][6], acc[o][7]);
        float s = 0.f, s2 = 0.f;
#pragma unroll
        for (int j = 0; j < 8; j++) { float v = acc[o][j]; s += v; s2 += v*v; }
        gs[o >> 1] += s; gs2[o >> 1] += s2;
    }
#pragma unroll
    for (int i = 0; i < 4; i++) {
        int grp = os*4 + i;
        atomicAdd(&sred[grp*2],     gs[i]);
        atomicAdd(&sred[grp*2 + 1], gs2[i]);
    }
    __syncthreads();
    if (tid < 16) atomicAdd(&stats[b*16 + tid], (double)sred[tid]);
}

// ---------------- GN finalize + apply + SiLU ----------------
// which: 0 = x1->x1n, 1 = x2->x2n, 2 = feat->outext
// grid = B*16*nslab, block = 256; each block handles one 8192-elem slab
__global__ void __launch_bounds__(256) k_norm(int which, float* outext,
                                              const float* __restrict__ gw,
                                              const float* __restrict__ gb,
                                              int nslab, float invN) {
    const float* in = (which == 0) ? g_x1 : (which == 1) ? g_x2 : g_feat;
    float* out = (which == 2) ? outext : ((which == 0) ? g_x1n : g_x2n);
    const double* st = g_stats + which*128;

    __shared__ float sA, sB;
    int x = blockIdx.x;
    int s = x % nslab;
    int c = (x / nslab) & 15;
    int b = x / (nslab*16);
    if (threadIdx.x == 0) {
        const double* p = st + ((size_t)b*8 + (c >> 1))*2;
        double mu = p[0] * (double)invN;
        double var = p[1] * (double)invN - mu*mu;
        float rstd = rsqrtf((float)var + 1e-5f);
        float A = rstd * gw[c];
        sA = A;
        sB = gb[c] - (float)mu * A;
    }
    __syncthreads();
    float A = sA, Bv = sB;

    size_t base = ((size_t)(b*16 + c)*nslab + s)*8192;
    const float4* ip = (const float4*)(in + base);
    float4* op = (float4*)(out + base);
    for (int i = threadIdx.x; i < 2048; i += 256) {
        float4 v = ip[i];
        v.x = v.x*A + Bv; v.y = v.y*A + Bv; v.z = v.z*A + Bv; v.w = v.w*A + Bv;
        v.x = v.x / (1.f + __expf(-v.x));
        v.y = v.y / (1.f + __expf(-v.y));
        v.z = v.z / (1.f + __expf(-v.z));
        v.w = v.w / (1.f + __expf(-v.w));
        op[i] = v;
    }
}

// ---------------- conv3d, 1 output channel (logits) ----------------
// grid = B*24*8, block = 128 ; thread: 1 oc x 8 w
__global__ void __launch_bounds__(128) k_conv3d_oc1(const float* __restrict__ wts,
                                                    const float* __restrict__ bias) {
    __shared__ float swt[432];
    int tid = threadIdx.x;
    for (int i = tid; i < 432; i += 128) swt[i] = wts[i];
    __syncthreads();

    int x = blockIdx.x;
    int ht = x & 7;
    int d = (x >> 3) % 24;
    int b = x / 192;
    int wt = tid & 15, hr = tid >> 4;
    int w0 = wt << 3, h = ht*8 + hr;

    float acc[8];
#pragma unroll
    for (int j = 0; j < 8; j++) acc[j] = 0.f;

    const float* inb = g_x2n + (size_t)b*16*DD*HW;
    for (int ic = 0; ic < 16; ic++) {
        const float* inc = inb + (size_t)ic*DD*HW;
#pragma unroll
        for (int kd = 0; kd < 3; kd++) {
            int zd = d + kd - 1;
            if ((unsigned)zd >= (unsigned)DD) continue;
#pragma unroll
            for (int kh = 0; kh < 3; kh++) {
                int zh = h + kh - 1;
                if ((unsigned)zh >= (unsigned)HH) continue;
                const float* row = inc + ((size_t)zd*HH + zh)*WW + w0;
                float r[10];
                r[0] = (w0 == 0) ? 0.f : __ldg(row - 1);
                float4 va = *(const float4*)row;
                float4 vb = *(const float4*)(row + 4);
                r[1] = va.x; r[2] = va.y; r[3] = va.z; r[4] = va.w;
                r[5] = vb.x; r[6] = vb.y; r[7] = vb.z; r[8] = vb.w;
                r[9] = (w0 == 120) ? 0.f : __ldg(row + 8);
                int tb = (kd*3 + kh)*3;
#pragma unroll
                for (int kw = 0; kw < 3; kw++) {
                    float wv = swt[ic*27 + tb + kw];
#pragma unroll
                    for (int j = 0; j < 8; j++)
                        acc[j] = fmaf(wv, r[j + kw], acc[j]);
                }
            }
        }
    }
    float bs = bias[0];
    float* orow = g_logits + (((size_t)b*DD + d)*HH + h)*WW + w0;
    *(float4*)orow       = make_float4(acc[0]+bs, acc[1]+bs, acc[2]+bs, acc[3]+bs);
    *(float4*)(orow + 4) = make_float4(acc[4]+bs, acc[5]+bs, acc[6]+bs, acc[7]+bs);
}

// ---------------- softmax over D -> d_out, conf; zero sx, sy ----------------
// grid = B*H, block = 128 (w)
__global__ void __launch_bounds__(128) k_softmax(float* __restrict__ out) {
    int x = blockIdx.x;
    int h = x & 63;
    int b = x >> 6;
    int w = threadIdx.x;
    const float* lp = g_logits + ((size_t)b*DD*HH + h)*WW + w;
    float l[DD];
    float m = -1e30f;
#pragma unroll
    for (int d = 0; d < DD; d++) { l[d] = lp[(size_t)d*HW]; m = fmaxf(m, l[d]); }
    float S = 0.f, E = 0.f;
#pragma unroll
    for (int d = 0; d < DD; d++) {
        float e = __expf(l[d] - m);
        S += e; E += e * (float)d;
    }
    float inv = 1.f / S;
    int oi = (b*HH + h)*WW + w;
    out[oi]           = E * inv;   // d_out
    out[65536 + oi]   = 0.f;       // sx
    out[131072 + oi]  = 0.f;       // sy
    out[1245184 + oi] = inv;       // conf = exp(max-max)/S
}

// ---------------- feature head conv2d (128->16 ch, 3x3) + GN stats ----------------
// grid = B*16*2, block = 128; thread: 4 oc x 8 w; weights staged in smem in 2 passes
__global__ void __launch_bounds__(128, 4) k_conv2d_feat(const float* __restrict__ fL,
                                                        const float* __restrict__ wts) {
    __shared__ __align__(16) float swt[64*144];   // [icl][tap][oc] for 64 input ch
    __shared__ float sred[16];
    int tid = threadIdx.x;
    if (tid < 16) sred[tid] = 0.f;

    int x = blockIdx.x;
    int wtile = x & 1;
    int ht = (x >> 1) & 15;
    int b = x >> 5;

    int wt = tid & 7, os = (tid >> 3) & 3, hr = tid >> 5;
    int w0 = wtile*64 + wt*8;
    int h = ht*4 + hr;
    int oc0 = os*4;

    float acc[4][8];
#pragma unroll
    for (int o = 0; o < 4; o++)
#pragma unroll
        for (int j = 0; j < 8; j++) acc[o][j] = 0.f;

    for (int p = 0; p < 2; p++) {
        __syncthreads();
        for (int i = tid; i < 64*144; i += 128) {
            int icl = i / 144; int r = i - icl*144; int tap = r >> 4; int oc = r & 15;
            swt[i] = wts[((size_t)oc*128 + p*64 + icl)*9 + tap];
        }
        __syncthreads();
        for (int icl = 0; icl < 64; icl++) {
            int ic = p*64 + icl;
            const float* rowb = fL + ((size_t)(b*128 + ic)*HH)*WW;
#pragma unroll
            for (int kh = 0; kh < 3; kh++) {
                int zh = h + kh - 1;
                if ((unsigned)zh >= (unsigned)HH) continue;
                const float* row = rowb + (size_t)zh*WW + w0;
                float r[10];
                r[0] = (w0 == 0) ? 0.f : __ldg(row - 1);
                float4 va = *(const float4*)row;
                float4 vb = *(const float4*)(row + 4);
                r[1] = va.x; r[2] = va.y; r[3] = va.z; r[4] = va.w;
                r[5] = vb.x; r[6] = vb.y; r[7] = vb.z; r[8] = vb.w;
                r[9] = (w0 == 120) ? 0.f : __ldg(row + 8);
#pragma unroll
                for (int kw = 0; kw < 3; kw++) {
                    const float4* wp = (const float4*)(swt + (icl*9 + kh*3 + kw)*16 + oc0);
                    float4 wv = *wp;
                    float wa[4] = {wv.x, wv.y, wv.z, wv.w};
#pragma unroll
                    for (int o = 0; o < 4; o++)
#pragma unroll
                        for (int j = 0; j < 8; j++)
                            acc[o][j] = fmaf(wa[o], r[j + kw], acc[o][j]);
                }
            }
        }
    }

    // store + stats (layer 2)
    float gs[2], gs2[2];
    gs[0] = gs[1] = gs2[0] = gs2[1] = 0.f;
#pragma unroll
    for (int o = 0; o < 4; o++) {
        int oc = oc0 + o;
        float* orow = g_feat + (((size_t)b*16 + oc)*HH + h)*WW + w0;
        *(float4*)orow       = make_float4(acc[o][0], acc[o][1], acc[o][2], acc[o][3]);
        *(float4*)(orow + 4) = make_float4(acc[o][4], acc[o][5], acc[o][6], acc[o][7]);
        float s = 0.f, s2 = 0.f;
#pragma unroll
        for (int j = 0; j < 8; j++) { float v = acc[o][j]; s += v; s2 += v*v; }
        gs[o >> 1] += s; gs2[o >> 1] += s2;
    }
#pragma unroll
    for (int i = 0; i < 2; i++) {
        int grp = os*2 + i;
        atomicAdd(&sred[grp*2],     gs[i]);
        atomicAdd(&sred[grp*2 + 1], gs2[i]);
    }
    __syncthreads();
    if (tid < 16) atomicAdd(&g_stats[2*128 + b*16 + tid], (double)sred[tid]);
}

// ---------------- launch ----------------
extern "C" void kernel_launch(void* const* d_in, const int* in_sizes, int n_in,
                              void* d_out, int out_size) {
    const float* fL    = (const float*)d_in[0];
    const float* fR    = (const float*)d_in[1];
    const float* w1    = (const float*)d_in[2];
    const float* gn1w  = (const float*)d_in[3];
    const float* gn1b  = (const float*)d_in[4];
    const float* w2    = (const float*)d_in[5];
    const float* gn2w  = (const float*)d_in[6];
    const float* gn2b  = (const float*)d_in[7];
    const float* w3    = (const float*)d_in[8];
    const float* b3    = (const float*)d_in[9];
    const float* fhw   = (const float*)d_in[10];
    const float* fhgnw = (const float*)d_in[11];
    const float* fhgnb = (const float*)d_in[12];
    float* out = (float*)d_out;

    const float invN3d = 1.0f / (2.0f*DD*HH*WW);   // 1/393216
    const float invN2d = 1.0f / (2.0f*HH*WW);      // 1/16384

    k_zero_stats<<<1, 384>>>();
    k_costvol<<<BATCH*8*HH, 128>>>(fL, fR);
    k_conv3d16<0><<<BATCH*24*16, 128>>>(w1);
    k_norm<<<BATCH*16*24, 256>>>(0, nullptr, gn1w, gn1b, 24, invN3d);
    k_conv3d16<1><<<BATCH*24*16, 128>>>(w2);
    k_norm<<<BATCH*16*24, 256>>>(1, nullptr, gn2w, gn2b, 24, invN3d);
    k_conv3d_oc1<<<BATCH*24*8, 128>>>(w3, b3);
    k_softmax<<<BATCH*HH, 128>>>(out);
    k_conv2d_feat<<<BATCH*16*2, 128>>>(fL, fhw);
    k_norm<<<BATCH*16, 256>>>(2, out + 196608, fhgnw, fhgnb, 1, invN2d);
}

// round 2
// speedup vs baseline: 1.0996x; 1.0996x over previous
#include <cuda_runtime.h>
#include <math.h>

#define BATCH 8
#define DD 24
#define HH 64
#define WW 128
#define HW (HH*WW)

typedef unsigned long long u64;

// ---------------- packed fp32x2 helpers (Blackwell dual-FP32 pipe) ----------------
__device__ __forceinline__ u64 pk(float lo, float hi) {
    u64 r; asm("mov.b64 %0, {%1,%2};" : "=l"(r) : "f"(lo), "f"(hi)); return r;
}
__device__ __forceinline__ u64 pk1(float v) { return pk(v, v); }
__device__ __forceinline__ void fma2(u64& d, u64 a, u64 b) {
    asm("fma.rn.f32x2 %0, %1, %2, %0;" : "+l"(d) : "l"(a), "l"(b));
}
__device__ __forceinline__ float2 unpk(u64 v) {
    float2 f; asm("mov.b64 {%0,%1}, %2;" : "=f"(f.x), "=f"(f.y) : "l"(v)); return f;
}

// ---------------- scratch (device globals; no allocations allowed) ----------------
__device__ float g_cv[BATCH*8*DD*HH*WW];        // cost volume (B,8,24,64,128)
__device__ float g_x1[BATCH*16*DD*HH*WW];       // conv1 raw
__device__ float g_x1n[BATCH*16*DD*HH*WW];      // conv1 GN+silu
__device__ float g_x2[BATCH*16*DD*HH*WW];       // conv2 raw
__device__ float g_x2n[BATCH*16*DD*HH*WW];      // conv2 GN+silu
__device__ float g_logits[BATCH*DD*HH*WW];      // conv3 output
__device__ float g_feat[BATCH*16*HH*WW];        // feat conv raw
__device__ double g_stats[3*BATCH*8*2];         // [layer][b][group][{sum,sumsq}]

// ---------------- zero stats ----------------
__global__ void k_zero_stats() {
    int i = threadIdx.x;
    if (i < 3*BATCH*8*2) g_stats[i] = 0.0;
}

// ---------------- cost volume ----------------
// grid = B*8*H, block = 128 (one thread per w)
__global__ void __launch_bounds__(128) k_costvol(const float* __restrict__ fL,
                                                 const float* __restrict__ fR) {
    __shared__ float sR[16*128];
    int x = blockIdx.x;
    int h = x & 63;
    int g = (x >> 6) & 7;
    int b = x >> 9;
    int tid = threadIdx.x;

    const float* baseL = fL + (((size_t)(b*128 + g*16))*HH + h)*WW;
    const float* baseR = fR + (((size_t)(b*128 + g*16))*HH + h)*WW;
    float l[16];
#pragma unroll
    for (int c = 0; c < 16; c++) {
        l[c] = baseL[(size_t)c*HW + tid];
        sR[c*128 + tid] = baseR[(size_t)c*HW + tid];
    }
    __syncthreads();

    float* ov = g_cv + (((size_t)(b*8 + g)*DD)*HH + h)*WW + tid;
    for (int d = 0; d < DD; d++) {
        float s = 0.f;
        if (tid >= d) {
#pragma unroll
            for (int c = 0; c < 16; c++) s += l[c] * sR[c*128 + tid - d];
            s *= 0.0625f;
        }
        ov[(size_t)d*HW] = s;
    }
}

// ---------------- conv3d, 16 output channels, fused GN stats, FMA2 ----------------
// LAYER 0: g_cv(CIN=8) -> g_x1 ; LAYER 1: g_x1n(CIN=16) -> g_x2
// grid = B*24*16, block = 128; thread: 8 oc (as 4 oc-pairs) x 8 w outputs
template<int LAYER>
__global__ void __launch_bounds__(128, 4) k_conv3d16(const float* __restrict__ wts) {
    constexpr int CIN = (LAYER == 0) ? 8 : 16;
    const float* in = (LAYER == 0) ? g_cv : g_x1n;
    float* out = (LAYER == 0) ? g_x1 : g_x2;
    double* stats = g_stats + LAYER*128;

    __shared__ __align__(16) float swt[CIN*432];   // [ic][tap][oc]  (oc contiguous -> float2 pairs)
    __shared__ float sred[16];
    int tid = threadIdx.x;
    for (int i = tid; i < CIN*432; i += 128) {
        int ic = i / 432; int r = i - ic*432; int tap = r >> 4; int oc = r & 15;
        swt[i] = wts[(oc*CIN + ic)*27 + tap];
    }
    if (tid < 16) sred[tid] = 0.f;
    __syncthreads();

    int x = blockIdx.x;
    int ht = x & 15;
    int d = (x >> 4) % 24;
    int b = x / 384;

    int wt = tid & 15, hr = (tid >> 4) & 3, os = tid >> 6;
    int w0 = wt << 3, h = (ht << 2) + hr, oc0 = os << 3;

    u64 acc[4][8];   // [oc-pair][w] ; lanes = (oc0+2op, oc0+2op+1)
#pragma unroll
    for (int o = 0; o < 4; o++)
#pragma unroll
        for (int j = 0; j < 8; j++) acc[o][j] = 0ull;

    const float* inb = in + (size_t)b*CIN*DD*HW;
    for (int ic = 0; ic < CIN; ic++) {
        const float* inc = inb + (size_t)ic*DD*HW;
#pragma unroll
        for (int kd = 0; kd < 3; kd++) {
            int zd = d + kd - 1;
            if ((unsigned)zd >= (unsigned)DD) continue;
#pragma unroll
            for (int kh = 0; kh < 3; kh++) {
                int zh = h + kh - 1;
                if ((unsigned)zh >= (unsigned)HH) continue;
                const float* row = inc + ((size_t)zd*HH + zh)*WW + w0;
                float e0 = (w0 == 0) ? 0.f : __ldg(row - 1);
                float4 va = *(const float4*)row;
                float4 vb = *(const float4*)(row + 4);
                float e9 = (w0 == 120) ? 0.f : __ldg(row + 8);
                u64 rp[10];
                rp[0] = pk1(e0);
                rp[1] = pk1(va.x); rp[2] = pk1(va.y); rp[3] = pk1(va.z); rp[4] = pk1(va.w);
                rp[5] = pk1(vb.x); rp[6] = pk1(vb.y); rp[7] = pk1(vb.z); rp[8] = pk1(vb.w);
                rp[9] = pk1(e9);
                int tb = (kd*3 + kh)*3;
#pragma unroll
                for (int kw = 0; kw < 3; kw++) {
                    const float* wbase = swt + ((ic*27 + tb + kw) << 4) + oc0;
#pragma unroll
                    for (int op = 0; op < 4; op++) {
                        u64 wv = *(const u64*)(wbase + 2*op);
#pragma unroll
                        for (int j = 0; j < 8; j++)
                            fma2(acc[op][j], wv, rp[j + kw]);
                    }
                }
            }
        }
    }

    // store + per-group partial stats (group = oc>>1 == os*4+op exactly per pair)
    float gs[4], gs2[4];
#pragma unroll
    for (int i = 0; i < 4; i++) { gs[i] = 0.f; gs2[i] = 0.f; }
#pragma unroll
    for (int op = 0; op < 4; op++) {
        float lo[8], hi[8];
#pragma unroll
        for (int j = 0; j < 8; j++) { float2 f = unpk(acc[op][j]); lo[j] = f.x; hi[j] = f.y; }
        int oc = oc0 + 2*op;
        float* orow0 = out + ((((size_t)b*16 + oc)*DD + d)*HH + h)*WW + w0;
        float* orow1 = orow0 + (size_t)DD*HW;
        *(float4*)orow0       = make_float4(lo[0], lo[1], lo[2], lo[3]);
        *(float4*)(orow0 + 4) = make_float4(lo[4], lo[5], lo[6], lo[7]);
        *(float4*)orow1       = make_float4(hi[0], hi[1], hi[2], hi[3]);
        *(float4*)(orow1 + 4) = make_float4(hi[4], hi[5], hi[6], hi[7]);
        float s = 0.f, s2 = 0.f;
#pragma unroll
        for (int j = 0; j < 8; j++) {
            s += lo[j] + hi[j];
            s2 += lo[j]*lo[j] + hi[j]*hi[j];
        }
        gs[op] += s; gs2[op] += s2;
    }
#pragma unroll
    for (int i = 0; i < 4; i++) {
        int grp = os*4 + i;
        atomicAdd(&sred[grp*2],     gs[i]);
        atomicAdd(&sred[grp*2 + 1], gs2[i]);
    }
    __syncthreads();
    if (tid < 16) atomicAdd(&stats[b*16 + tid], (double)sred[tid]);
}

// ---------------- GN finalize + apply + SiLU ----------------
// which: 0 = x1->x1n, 1 = x2->x2n, 2 = feat->outext
__global__ void __launch_bounds__(256) k_norm(int which, float* outext,
                                              const float* __restrict__ gw,
                                              const float* __restrict__ gb,
                                              int nslab, float invN) {
    const float* in = (which == 0) ? g_x1 : (which == 1) ? g_x2 : g_feat;
    float* out = (which == 2) ? outext : ((which == 0) ? g_x1n : g_x2n);
    const double* st = g_stats + which*128;

    __shared__ float sA, sB;
    int x = blockIdx.x;
    int s = x % nslab;
    int c = (x / nslab) & 15;
    int b = x / (nslab*16);
    if (threadIdx.x == 0) {
        const double* p = st + ((size_t)b*8 + (c >> 1))*2;
        double mu = p[0] * (double)invN;
        double var = p[1] * (double)invN - mu*mu;
        float rstd = rsqrtf((float)var + 1e-5f);
        float A = rstd * gw[c];
        sA = A;
        sB = gb[c] - (float)mu * A;
    }
    __syncthreads();
    float A = sA, Bv = sB;

    size_t base = ((size_t)(b*16 + c)*nslab + s)*8192;
    const float4* ip = (const float4*)(in + base);
    float4* op = (float4*)(out + base);
    for (int i = threadIdx.x; i < 2048; i += 256) {
        float4 v = ip[i];
        v.x = v.x*A + Bv; v.y = v.y*A + Bv; v.z = v.z*A + Bv; v.w = v.w*A + Bv;
        v.x = v.x / (1.f + __expf(-v.x));
        v.y = v.y / (1.f + __expf(-v.y));
        v.z = v.z / (1.f + __expf(-v.z));
        v.w = v.w / (1.f + __expf(-v.w));
        op[i] = v;
    }
}

// ---------------- conv3d, 1 output channel (logits), FMA2 over w-pairs ----------------
// grid = B*24*8, block = 128 ; thread: 1 oc x 8 w (4 w-pairs)
__global__ void __launch_bounds__(128) k_conv3d_oc1(const float* __restrict__ wts,
                                                    const float* __restrict__ bias) {
    __shared__ float swt[432];
    int tid = threadIdx.x;
    for (int i = tid; i < 432; i += 128) swt[i] = wts[i];
    __syncthreads();

    int x = blockIdx.x;
    int ht = x & 7;
    int d = (x >> 3) % 24;
    int b = x / 192;
    int wt = tid & 15, hr = tid >> 4;
    int w0 = wt << 3, h = ht*8 + hr;

    u64 acc[4];   // w-pairs (2t, 2t+1)
#pragma unroll
    for (int t = 0; t < 4; t++) acc[t] = 0ull;

    const float* inb = g_x2n + (size_t)b*16*DD*HW;
    for (int ic = 0; ic < 16; ic++) {
        const float* inc = inb + (size_t)ic*DD*HW;
#pragma unroll
        for (int kd = 0; kd < 3; kd++) {
            int zd = d + kd - 1;
            if ((unsigned)zd >= (unsigned)DD) continue;
#pragma unroll
            for (int kh = 0; kh < 3; kh++) {
                int zh = h + kh - 1;
                if ((unsigned)zh >= (unsigned)HH) continue;
                const float* row = inc + ((size_t)zd*HH + zh)*WW + w0;
                float r[10];
                r[0] = (w0 == 0) ? 0.f : __ldg(row - 1);
                float4 va = *(const float4*)row;
                float4 vb = *(const float4*)(row + 4);
                r[1] = va.x; r[2] = va.y; r[3] = va.z; r[4] = va.w;
                r[5] = vb.x; r[6] = vb.y; r[7] = vb.z; r[8] = vb.w;
                r[9] = (w0 == 120) ? 0.f : __ldg(row + 8);
                // even-aligned pairs (r0,r1)(r2,r3)(r4,r5)(r6,r7)(r8,r9), odd (r1,r2)...
                u64 pe[5], po[4];
#pragma unroll
                for (int t = 0; t < 5; t++) pe[t] = pk(r[2*t], r[2*t + 1]);
#pragma unroll
                for (int t = 0; t < 4; t++) po[t] = pk(r[2*t + 1], r[2*t + 2]);
                int tb = (kd*3 + kh)*3;
                u64 wv0 = pk1(swt[ic*27 + tb + 0]);
                u64 wv1 = pk1(swt[ic*27 + tb + 1]);
                u64 wv2 = pk1(swt[ic*27 + tb + 2]);
#pragma unroll
                for (int t = 0; t < 4; t++) {
                    fma2(acc[t], wv0, pe[t]);       // r[2t+0], r[2t+1]
                    fma2(acc[t], wv1, po[t]);       // r[2t+1], r[2t+2]
                    fma2(acc[t], wv2, pe[t + 1]);   // r[2t+2], r[2t+3]
                }
            }
        }
    }
    float bs = bias[0];
    float o[8];
#pragma unroll
    for (int t = 0; t < 4; t++) { float2 f = unpk(acc[t]); o[2*t] = f.x + bs; o[2*t+1] = f.y + bs; }
    float* orow = g_logits + (((size_t)b*DD + d)*HH + h)*WW + w0;
    *(float4*)orow       = make_float4(o[0], o[1], o[2], o[3]);
    *(float4*)(orow + 4) = make_float4(o[4], o[5], o[6], o[7]);
}

// ---------------- softmax over D -> d_out, conf; zero sx, sy ----------------
__global__ void __launch_bounds__(128) k_softmax(float* __restrict__ out) {
    int x = blockIdx.x;
    int h = x & 63;
    int b = x >> 6;
    int w = threadIdx.x;
    const float* lp = g_logits + ((size_t)b*DD*HH + h)*WW + w;
    float l[DD];
    float m = -1e30f;
#pragma unroll
    for (int d = 0; d < DD; d++) { l[d] = lp[(size_t)d*HW]; m = fmaxf(m, l[d]); }
    float S = 0.f, E = 0.f;
#pragma unroll
    for (int d = 0; d < DD; d++) {
        float e = __expf(l[d] - m);
        S += e; E += e * (float)d;
    }
    float inv = 1.f / S;
    int oi = (b*HH + h)*WW + w;
    out[oi]           = E * inv;   // d_out
    out[65536 + oi]   = 0.f;       // sx
    out[131072 + oi]  = 0.f;       // sy
    out[1245184 + oi] = inv;       // conf = exp(max-max)/S
}

// ---------------- feature head conv2d (128->16 ch, 3x3) + GN stats, FMA2 ----------------
// grid = B*16*2, block = 128; thread: 4 oc (2 oc-pairs) x 8 w
__global__ void __launch_bounds__(128, 4) k_conv2d_feat(const float* __restrict__ fL,
                                                        const float* __restrict__ wts) {
    __shared__ __align__(16) float swt[64*144];   // [icl][tap][oc] for 64 input ch
    __shared__ float sred[16];
    int tid = threadIdx.x;
    if (tid < 16) sred[tid] = 0.f;

    int x = blockIdx.x;
    int wtile = x & 1;
    int ht = (x >> 1) & 15;
    int b = x >> 5;

    int wt = tid & 7, os = (tid >> 3) & 3, hr = tid >> 5;
    int w0 = wtile*64 + wt*8;
    int h = ht*4 + hr;
    int oc0 = os*4;

    u64 acc[2][8];
#pragma unroll
    for (int o = 0; o < 2; o++)
#pragma unroll
        for (int j = 0; j < 8; j++) acc[o][j] = 0ull;

    for (int p = 0; p < 2; p++) {
        __syncthreads();
        for (int i = tid; i < 64*144; i += 128) {
            int icl = i / 144; int r = i - icl*144; int tap = r >> 4; int oc = r & 15;
            swt[i] = wts[((size_t)oc*128 + p*64 + icl)*9 + tap];
        }
        __syncthreads();
        for (int icl = 0; icl < 64; icl++) {
            int ic = p*64 + icl;
            const float* rowb = fL + ((size_t)(b*128 + ic)*HH)*WW;
#pragma unroll
            for (int kh = 0; kh < 3; kh++) {
                int zh = h + kh - 1;
                if ((unsigned)zh >= (unsigned)HH) continue;
                const float* row = rowb + (size_t)zh*WW + w0;
                float e0 = (w0 == 0) ? 0.f : __ldg(row - 1);
                float4 va = *(const float4*)row;
                float4 vb = *(const float4*)(row + 4);
                float e9 = (w0 == 120) ? 0.f : __ldg(row + 8);
                u64 rp[10];
                rp[0] = pk1(e0);
                rp[1] = pk1(va.x); rp[2] = pk1(va.y); rp[3] = pk1(va.z); rp[4] = pk1(va.w);
                rp[5] = pk1(vb.x); rp[6] = pk1(vb.y); rp[7] = pk1(vb.z); rp[8] = pk1(vb.w);
                rp[9] = pk1(e9);
#pragma unroll
                for (int kw = 0; kw < 3; kw++) {
                    const float* wbase = swt + (icl*9 + kh*3 + kw)*16 + oc0;
#pragma unroll
                    for (int op = 0; op < 2; op++) {
                        u64 wv = *(const u64*)(wbase + 2*op);
#pragma unroll
                        for (int j = 0; j < 8; j++)
                            fma2(acc[op][j], wv, rp[j + kw]);
                    }
                }
            }
        }
    }

    // store + stats (layer 2); pair (oc0+2op, oc0+2op+1) is exactly group (oc0>>1)+op
    float gs[2], gs2[2];
    gs[0] = gs[1] = gs2[0] = gs2[1] = 0.f;
#pragma unroll
    for (int op = 0; op < 2; op++) {
        float lo[8], hi[8];
#pragma unroll
        for (int j = 0; j < 8; j++) { float2 f = unpk(acc[op][j]); lo[j] = f.x; hi[j] = f.y; }
        int oc = oc0 + 2*op;
        float* orow0 = g_feat + (((size_t)b*16 + oc)*HH + h)*WW + w0;
        float* orow1 = orow0 + (size_t)HW;
        *(float4*)orow0       = make_float4(lo[0], lo[1], lo[2], lo[3]);
        *(float4*)(orow0 + 4) = make_float4(lo[4], lo[5], lo[6], lo[7]);
        *(float4*)orow1       = make_float4(hi[0], hi[1], hi[2], hi[3]);
        *(float4*)(orow1 + 4) = make_float4(hi[4], hi[5], hi[6], hi[7]);
        float s = 0.f, s2 = 0.f;
#pragma unroll
        for (int j = 0; j < 8; j++) {
            s += lo[j] + hi[j];
            s2 += lo[j]*lo[j] + hi[j]*hi[j];
        }
        gs[op] += s; gs2[op] += s2;
    }
#pragma unroll
    for (int i = 0; i < 2; i++) {
        int grp = os*2 + i;
        atomicAdd(&sred[grp*2],     gs[i]);
        atomicAdd(&sred[grp*2 + 1], gs2[i]);
    }
    __syncthreads();
    if (tid < 16) atomicAdd(&g_stats[2*128 + b*16 + tid], (double)sred[tid]);
}

// ---------------- launch ----------------
extern "C" void kernel_launch(void* const* d_in, const int* in_sizes, int n_in,
                              void* d_out, int out_size) {
    const float* fL    = (const float*)d_in[0];
    const float* fR    = (const float*)d_in[1];
    const float* w1    = (const float*)d_in[2];
    const float* gn1w  = (const float*)d_in[3];
    const float* gn1b  = (const float*)d_in[4];
    const float* w2    = (const float*)d_in[5];
    const float* gn2w  = (const float*)d_in[6];
    const float* gn2b  = (const float*)d_in[7];
    const float* w3    = (const float*)d_in[8];
    const float* b3    = (const float*)d_in[9];
    const float* fhw   = (const float*)d_in[10];
    const float* fhgnw = (const float*)d_in[11];
    const float* fhgnb = (const float*)d_in[12];
    float* out = (float*)d_out;

    const float invN3d = 1.0f / (2.0f*DD*HH*WW);   // 1/393216
    const float invN2d = 1.0f / (2.0f*HH*WW);      // 1/16384

    k_zero_stats<<<1, 384>>>();
    k_costvol<<<BATCH*8*HH, 128>>>(fL, fR);
    k_conv3d16<0><<<BATCH*24*16, 128>>>(w1);
    k_norm<<<BATCH*16*24, 256>>>(0, nullptr, gn1w, gn1b, 24, invN3d);
    k_conv3d16<1><<<BATCH*24*16, 128>>>(w2);
    k_norm<<<BATCH*16*24, 256>>>(1, nullptr, gn2w, gn2b, 24, invN3d);
    k_conv3d_oc1<<<BATCH*24*8, 128>>>(w3, b3);
    k_softmax<<<BATCH*HH, 128>>>(out);
    k_conv2d_feat<<<BATCH*16*2, 128>>>(fL, fhw);
    k_norm<<<BATCH*16, 256>>>(2, out + 196608, fhgnw, fhgnb, 1, invN2d);
}